// round 8
// baseline (speedup 1.0000x reference)
#include <cuda_runtime.h>
#include <math.h>
#include <stdint.h>

#define Bv 2
#define Tv 2048
#define Cv 768
#define Hv 12
#define BTv 4096
typedef unsigned long long ull;

__device__ float g_Q[Bv*Hv*64*Tv];   // [b,h,d,t]  (transposed)
__device__ float g_K[Bv*Hv*64*Tv];   // [b,h,d,t]  (transposed)
__device__ float g_V[Bv*Hv*Tv*64];   // [b,h,t,d]
__device__ float g_Y[BTv*Cv];

__device__ __forceinline__ ull pk2(float lo, float hi) {
    ull r; asm("mov.b64 %0, {%1, %2};" : "=l"(r) : "f"(lo), "f"(hi)); return r;
}
__device__ __forceinline__ void fma2(ull& d, ull a, ull b) {
    asm("fma.rn.f32x2 %0, %1, %2, %3;" : "=l"(d) : "l"(a), "l"(b), "l"(d));
}
__device__ __forceinline__ void upk(ull p, float& lo, float& hi) {
    asm("mov.b64 {%0, %1}, %2;" : "=f"(lo), "=f"(hi) : "l"(p));
}
__device__ __forceinline__ unsigned int saddr(const void* p) {
    return (unsigned int)__cvta_generic_to_shared(p);
}
__device__ __forceinline__ void cpa16(unsigned int dst, const void* src) {
    asm volatile("cp.async.cg.shared.global [%0], [%1], 16;" :: "r"(dst), "l"(src));
}
__device__ __forceinline__ void cpa_commit() { asm volatile("cp.async.commit_group;"); }
template<int N> __device__ __forceinline__ void cpa_wait() {
    asm volatile("cp.async.wait_group %0;" :: "n"(N));
}
__device__ __forceinline__ unsigned int ordf(float f) {
    unsigned int u = __float_as_uint(f);
    return u ^ (unsigned int)(((int)u >> 31) | 0x80000000);
}
__device__ __forceinline__ float deord(unsigned int u) {
    unsigned int bits = (u & 0x80000000u) ? (u ^ 0x80000000u) : ~u;
    return __uint_as_float(bits);
}

// ---------------------------------------------------------------------------
// GEMM: BM=128 BN=128 BK=16, 8x8 via f32x2.
// Epilogue: mode 0/1 -> g_Q/g_K TRANSPOSED [b,h,d,t] (mode 0 * log(T)*qm);
//           mode 2 -> g_V [b,h,t,d]; mode 3 -> outp row-major.
// ---------------------------------------------------------------------------
__global__ __launch_bounds__(256, 2) void gemm_kernel(
    const float* __restrict__ A, const float* __restrict__ Wq,
    const float* __restrict__ Wk, const float* __restrict__ Wv,
    const float* __restrict__ qm, float* __restrict__ outp, int mode_base)
{
    __shared__ float As[2][16*132];
    __shared__ float Bs[2][16*132];

    const int mode = mode_base + blockIdx.z;
    const float* W  = (mode == 0) ? Wq : (mode == 1) ? Wk : (mode == 2) ? Wv : Wq;
    const float* Ap = (mode == 3) ? (const float*)g_Y : A;

    const int tid = threadIdx.x;
    const int ty = tid >> 4, tx = tid & 15;
    const int m0 = blockIdx.x * 128, n0 = blockIdx.y * 128;
    const int arow = tid >> 2, ac4 = tid & 3;
    const int brow = tid >> 5, bc4 = tid & 31;
    const float* aG = Ap + (size_t)(m0 + arow) * 768 + ac4 * 4;
    const float* bG = W + (size_t)brow * 768 + n0 + bc4 * 4;

    ull acc2[8][4];
    #pragma unroll
    for (int r = 0; r < 8; r++)
        #pragma unroll
        for (int c = 0; c < 4; c++) acc2[r][c] = 0ull;

    float4 ra0 = *(const float4*)aG;
    float4 ra1 = *(const float4*)(aG + (size_t)64 * 768);
    float4 rb0 = *(const float4*)bG;
    float4 rb1 = *(const float4*)(bG + (size_t)8 * 768);

    #pragma unroll 1
    for (int kt = 0; kt < 48; kt++) {
        {
            float* as = As[kt & 1]; float* bs = Bs[kt & 1];
            as[(ac4*4+0)*132 + arow] = ra0.x; as[(ac4*4+1)*132 + arow] = ra0.y;
            as[(ac4*4+2)*132 + arow] = ra0.z; as[(ac4*4+3)*132 + arow] = ra0.w;
            as[(ac4*4+0)*132 + arow+64] = ra1.x; as[(ac4*4+1)*132 + arow+64] = ra1.y;
            as[(ac4*4+2)*132 + arow+64] = ra1.z; as[(ac4*4+3)*132 + arow+64] = ra1.w;
            *(float4*)&bs[brow*132 + bc4*4] = rb0;
            *(float4*)&bs[(brow+8)*132 + bc4*4] = rb1;
        }
        __syncthreads();
        if (kt < 47) {
            ra0 = *(const float4*)(aG + (kt+1)*16);
            ra1 = *(const float4*)(aG + (size_t)64*768 + (kt+1)*16);
            rb0 = *(const float4*)(bG + (size_t)(kt+1)*16*768);
            rb1 = *(const float4*)(bG + (size_t)(kt+1)*16*768 + (size_t)8*768);
        }
        const float* as = As[kt & 1]; const float* bs = Bs[kt & 1];
        #pragma unroll
        for (int kk = 0; kk < 16; kk++) {
            float4 a0 = *(const float4*)&as[kk*132 + ty*8];
            float4 a1 = *(const float4*)&as[kk*132 + ty*8 + 4];
            ulonglong2 b0 = *(const ulonglong2*)&bs[kk*132 + tx*4];
            ulonglong2 b1 = *(const ulonglong2*)&bs[kk*132 + 64 + tx*4];
            ull ad[8] = { pk2(a0.x,a0.x), pk2(a0.y,a0.y), pk2(a0.z,a0.z), pk2(a0.w,a0.w),
                          pk2(a1.x,a1.x), pk2(a1.y,a1.y), pk2(a1.z,a1.z), pk2(a1.w,a1.w) };
            #pragma unroll
            for (int r = 0; r < 8; r++) {
                fma2(acc2[r][0], ad[r], b0.x);
                fma2(acc2[r][1], ad[r], b0.y);
                fma2(acc2[r][2], ad[r], b1.x);
                fma2(acc2[r][3], ad[r], b1.y);
            }
        }
        __syncthreads();
    }

    float accf[8][8];
    #pragma unroll
    for (int r = 0; r < 8; r++) {
        upk(acc2[r][0], accf[r][0], accf[r][1]);
        upk(acc2[r][1], accf[r][2], accf[r][3]);
        upk(acc2[r][2], accf[r][4], accf[r][5]);
        upk(acc2[r][3], accf[r][6], accf[r][7]);
    }

    if (mode == 3) {
        #pragma unroll
        for (int r = 0; r < 8; r++) {
            int row = m0 + ty*8 + r;
            *(float4*)(outp + (size_t)row*768 + n0 + tx*4) =
                make_float4(accf[r][0], accf[r][1], accf[r][2], accf[r][3]);
            *(float4*)(outp + (size_t)row*768 + n0 + 64 + tx*4) =
                make_float4(accf[r][4], accf[r][5], accf[r][6], accf[r][7]);
        }
    } else if (mode == 2) {
        const int h0 = n0 >> 6, d0 = tx*4;
        #pragma unroll
        for (int r = 0; r < 8; r++) {
            int row = m0 + ty*8 + r;
            int bb = row >> 11, t = row & 2047;
            size_t p0 = ((size_t)(bb*Hv + h0)*Tv + t)*64 + d0;
            size_t p1 = ((size_t)(bb*Hv + h0 + 1)*Tv + t)*64 + d0;
            *(float4*)(g_V + p0) = make_float4(accf[r][0], accf[r][1], accf[r][2], accf[r][3]);
            *(float4*)(g_V + p1) = make_float4(accf[r][4], accf[r][5], accf[r][6], accf[r][7]);
        }
    } else {
        float* dst = (mode == 0) ? g_Q : g_K;
        const int h0 = n0 >> 6, d0 = tx*4;
        const int row0 = m0 + ty*8;
        const int bb = row0 >> 11, t0 = row0 & 2047;
        float s[4] = {1.f, 1.f, 1.f, 1.f};
        if (mode == 0) {
            const float LT = 7.6246189861593985f;   // log(2048)
            s[0] = LT*qm[d0]; s[1] = LT*qm[d0+1]; s[2] = LT*qm[d0+2]; s[3] = LT*qm[d0+3];
        }
        #pragma unroll
        for (int c = 0; c < 4; c++) {
            size_t a0 = ((size_t)(bb*Hv + h0)*64 + d0 + c)*Tv + t0;
            size_t a1 = ((size_t)(bb*Hv + h0 + 1)*64 + d0 + c)*Tv + t0;
            *(float4*)(dst + a0)     = make_float4(accf[0][c]*s[c], accf[1][c]*s[c],
                                                   accf[2][c]*s[c], accf[3][c]*s[c]);
            *(float4*)(dst + a0 + 4) = make_float4(accf[4][c]*s[c], accf[5][c]*s[c],
                                                   accf[6][c]*s[c], accf[7][c]*s[c]);
            *(float4*)(dst + a1)     = make_float4(accf[0][c+4]*s[c], accf[1][c+4]*s[c],
                                                   accf[2][c+4]*s[c], accf[3][c+4]*s[c]);
            *(float4*)(dst + a1 + 4) = make_float4(accf[4][c+4]*s[c], accf[5][c+4]*s[c],
                                                   accf[6][c+4]*s[c], accf[7][c+4]*s[c]);
        }
    }
}

// ---------------------------------------------------------------------------
// Attention v3b: Q,K in [d][t] smem (stride 132), 128q x 128k per block,
// 8q x 8k per thread, f32x2 packed along queries, 3-stage cp.async K ring.
// ---------------------------------------------------------------------------
#define AST 132
__global__ __launch_bounds__(256, 1) void attn_kernel()
{
    extern __shared__ float sm[];
    float* Qs = sm;                             // [64][AST]
    float* Kb[3] = { sm + 64*AST, sm + 2*64*AST, sm + 3*64*AST };

    const int tid = threadIdx.x;
    const int tq = tid >> 4, tk = tid & 15;
    const int qt = 15 - (int)blockIdx.x;        // heavy first
    const int h = blockIdx.y, b = blockIdx.z;
    const size_t bhT = (size_t)(b*Hv + h) * 64 * Tv;
    const size_t bhV = (size_t)(b*Hv + h) * Tv * 64;

    #pragma unroll
    for (int it = 0; it < 8; it++) {
        int i = it*256 + tid;
        int row = i >> 5, ch = i & 31;
        cpa16(saddr(Qs + row*AST + ch*4), g_Q + bhT + (size_t)row*Tv + qt*128 + ch*4);
        cpa16(saddr(Kb[0] + row*AST + ch*4), g_K + bhT + (size_t)row*Tv + ch*4);
    }
    cpa_commit();
    {
        int t1 = (qt >= 1) ? 1 : 0;
        #pragma unroll
        for (int it = 0; it < 8; it++) {
            int i = it*256 + tid;
            int row = i >> 5, ch = i & 31;
            cpa16(saddr(Kb[1] + row*AST + ch*4), g_K + bhT + (size_t)row*Tv + t1*128 + ch*4);
        }
        cpa_commit();
    }

    ull top[8][4];
    #pragma unroll
    for (int q = 0; q < 8; q++)
        #pragma unroll
        for (int m = 0; m < 4; m++) top[q][m] = 0ull;   // sentinel

    int qg[8];
    #pragma unroll
    for (int q = 0; q < 8; q++)
        qg[q] = qt*128 + ((q < 4) ? (tq*4 + q) : (64 + tq*4 + (q-4)));

    for (int kt = 0; kt <= qt; kt++) {
        cpa_wait<1>();
        __syncthreads();
        if (kt + 2 <= qt) {
            float* nb = Kb[(kt+2)%3];
            #pragma unroll
            for (int it = 0; it < 8; it++) {
                int i = it*256 + tid;
                int row = i >> 5, ch = i & 31;
                cpa16(saddr(nb + row*AST + ch*4),
                      g_K + bhT + (size_t)row*Tv + (kt+2)*128 + ch*4);
            }
        }
        cpa_commit();

        const float* kb = Kb[kt%3];
        ull acc2[4][8];
        #pragma unroll
        for (int p = 0; p < 4; p++)
            #pragma unroll
            for (int j = 0; j < 8; j++) acc2[p][j] = 0ull;

        #pragma unroll 8
        for (int d = 0; d < 64; d++) {
            ulonglong2 qa = *(const ulonglong2*)(Qs + d*AST + tq*4);
            ulonglong2 qb = *(const ulonglong2*)(Qs + d*AST + 64 + tq*4);
            float4 k0 = *(const float4*)(kb + d*AST + tk*4);
            float4 k1 = *(const float4*)(kb + d*AST + 64 + tk*4);
            ull kd[8] = { pk2(k0.x,k0.x), pk2(k0.y,k0.y), pk2(k0.z,k0.z), pk2(k0.w,k0.w),
                          pk2(k1.x,k1.x), pk2(k1.y,k1.y), pk2(k1.z,k1.z), pk2(k1.w,k1.w) };
            #pragma unroll
            for (int j = 0; j < 8; j++) {
                fma2(acc2[0][j], qa.x, kd[j]);
                fma2(acc2[1][j], qa.y, kd[j]);
                fma2(acc2[2][j], qb.x, kd[j]);
                fma2(acc2[3][j], qb.y, kd[j]);
            }
        }

        #pragma unroll
        for (int p = 0; p < 4; p++) {
            #pragma unroll
            for (int j = 0; j < 8; j++) {
                int jglob = kt*128 + ((j < 4) ? (tk*4 + j) : (64 + tk*4 + (j-4)));
                float se, so; upk(acc2[p][j], se, so);
                #pragma unroll
                for (int e = 0; e < 2; e++) {
                    int q = p*2 + e;
                    float s = (e ? so : se) * 0.125f;
                    if (jglob <= qg[q]) {
                        ull key = ((ull)ordf(s) << 32) | (unsigned int)jglob;
                        if (key > top[q][3]) {
                            if (key > top[q][1]) {
                                top[q][3] = top[q][2]; top[q][2] = top[q][1];
                                if (key > top[q][0]) { top[q][1] = top[q][0]; top[q][0] = key; }
                                else top[q][1] = key;
                            } else {
                                if (key > top[q][2]) { top[q][3] = top[q][2]; top[q][2] = key; }
                                else top[q][3] = key;
                            }
                        }
                    }
                }
            }
        }
    }

    #pragma unroll
    for (int msk = 1; msk <= 8; msk <<= 1) {
        #pragma unroll
        for (int q = 0; q < 8; q++) {
            ull bo[4];
            #pragma unroll
            for (int r = 0; r < 4; r++)
                bo[r] = __shfl_xor_sync(0xffffffffu, top[q][r], msk);
            ull mv[4];
            #pragma unroll
            for (int r = 0; r < 4; r++)
                mv[r] = (top[q][r] >= bo[3-r]) ? top[q][r] : bo[3-r];
            #define CEP(x, y) do { if (mv[x] < mv[y]) { ull t_ = mv[x]; mv[x] = mv[y]; mv[y] = t_; } } while (0)
            CEP(0,2); CEP(1,3); CEP(0,1); CEP(2,3);
            #undef CEP
            #pragma unroll
            for (int r = 0; r < 4; r++) top[q][r] = mv[r];
        }
    }

    const ull SENT = 1ull << 32;
    const ull ZKEY = (ull)0x80000000u << 32;
    #pragma unroll
    for (int q = 0; q < 8; q++) {
        int iglob = qg[q];
        int nz = Tv - (iglob + 1);
        float v0 = deord((unsigned int)(top[q][0] >> 32));
        float v1 = deord((unsigned int)(top[q][1] >> 32));
        float v2 = deord((unsigned int)(top[q][2] >> 32));
        float v3 = deord((unsigned int)(top[q][3] >> 32));
        int p = (top[q][0] > ZKEY) + (top[q][1] > ZKEY) + (top[q][2] > ZKEY) + (top[q][3] > ZKEY);
        float kth;
        if (p >= 4) kth = v3;
        else if (nz >= 4 - p) kth = 0.0f;
        else {
            int ix = 3 - nz;
            kth = (ix == 0) ? v0 : (ix == 1) ? v1 : (ix == 2) ? v2 : v3;
        }
        float vals[4] = {v0, v1, v2, v3};
        float a0 = 0.f, a1 = 0.f, a2 = 0.f, a3 = 0.f;
        #pragma unroll
        for (int m = 0; m < 4; m++) {
            if (top[q][m] >= SENT && vals[m] >= kth) {
                float w = tanhf(vals[m]);
                int idx = (int)(top[q][m] & 0xFFFFFFFFull);
                float4 vv = *(const float4*)(g_V + bhV + (size_t)idx*64 + tk*4);
                a0 += w*vv.x; a1 += w*vv.y; a2 += w*vv.z; a3 += w*vv.w;
            }
        }
        *(float4*)(g_Y + (size_t)(b*Tv + iglob)*Cv + h*64 + tk*4) =
            make_float4(a0, a1, a2, a3);
    }
}

extern "C" void kernel_launch(void* const* d_in, const int* in_sizes, int n_in,
                              void* d_out, int out_size)
{
    (void)in_sizes; (void)n_in; (void)out_size;
    const float* x  = (const float*)d_in[0];
    const float* Wq = (const float*)d_in[1];
    const float* Wk = (const float*)d_in[2];
    const float* Wv = (const float*)d_in[3];
    const float* Wp = (const float*)d_in[4];
    const float* qm = (const float*)d_in[5];
    float* out = (float*)d_out;

    const int attn_smem = 4 * 64 * AST * 4;   // Qs + 3 K buffers = 135168 B
    cudaFuncSetAttribute(attn_kernel, cudaFuncAttributeMaxDynamicSharedMemorySize, attn_smem);

    dim3 blk(256);
    gemm_kernel<<<dim3(32, 6, 3), blk>>>(x, Wq, Wk, Wv, qm, nullptr, 0);
    attn_kernel<<<dim3(16, 12, 2), blk, attn_smem>>>();
    gemm_kernel<<<dim3(32, 6, 1), blk>>>(nullptr, Wp, Wp, Wp, qm, out, 3);
}